// round 12
// baseline (speedup 1.0000x reference)
#include <cuda_runtime.h>
#include <cuda_bf16.h>
#include <cstdint>
#include <math.h>

#define NIMG 128
#define OCH 256
#define C1 537

// SMEM: double-buffered stage = A(2x32KB hi/lo) + B(2x14KB hi/lo) = 94208 B
#define STG 94208
#define ASM(b,hl) ((b)*STG + (hl)*32768)            // A: 256 rows x 128B
#define BSM(b,hl) ((b)*STG + 65536 + (hl)*14336)    // B: 112 rows x 128B
#define SMEMSZ (2*STG)                              // 188416 B
#define SWZ(x) ((x) ^ (((x)>>3)&0x70))

__device__ __constant__ int c_dh[9] = {-1,-1,-1,0,0,-2,0,2,3};
__device__ __constant__ int c_dw[9] = {-3,-1,1,0,2,1,-1,0,1};

__device__ __align__(128) float         g_pooled[(size_t)NIMG*25*784];
__device__ __align__(128) __nv_bfloat16 g_in [(size_t)NIMG*784*2*576];
__device__ __align__(128) __nv_bfloat16 g_yA [(size_t)NIMG*784*2*256];
__device__ __align__(128) __nv_bfloat16 g_yB [(size_t)NIMG*784*2*256];
__device__ __align__(128) __nv_bfloat16 g_w1p[(size_t)81*2*256*64];
__device__ __align__(128) __nv_bfloat16 g_w2p[(size_t)36*2*256*64];
__device__ __align__(128) __nv_bfloat16 g_w3p[(size_t)36*2*256*64];
__device__ __align__(128) __nv_bfloat16 g_w4p[(size_t)36*2*256*64];

__device__ __forceinline__ uint32_t smem_u32(const void* p) {
    uint32_t a;
    asm("{ .reg .u64 t; cvta.to.shared.u64 t, %1; cvt.u32.u64 %0, t; }" : "=r"(a) : "l"(p));
    return a;
}
__device__ __forceinline__ void cpa(uint32_t dst, const void* src, uint32_t sz) {
    asm volatile("cp.async.cg.shared.global [%0], [%1], 16, %2;" :: "r"(dst), "l"(src), "r"(sz));
}
#define CP_COMMIT() asm volatile("cp.async.commit_group;" ::: "memory")
#define CP_WAIT1()  asm volatile("cp.async.wait_group 1;" ::: "memory")
#define CP_WAIT0()  asm volatile("cp.async.wait_group 0;" ::: "memory")
#define LDSM4(r,a) asm volatile("ldmatrix.sync.aligned.m8n8.x4.shared.b16 {%0,%1,%2,%3}, [%4];" \
    : "=r"((r)[0]),"=r"((r)[1]),"=r"((r)[2]),"=r"((r)[3]) : "r"(a))
#define LDSM2(r,a) asm volatile("ldmatrix.sync.aligned.m8n8.x2.shared.b16 {%0,%1}, [%2];" \
    : "=r"((r)[0]),"=r"((r)[1]) : "r"(a))
#define MMA(d,a,b) asm volatile( \
    "mma.sync.aligned.m16n8k16.row.col.f32.bf16.bf16.f32 {%0,%1,%2,%3}, {%4,%5,%6,%7}, {%8,%9}, {%0,%1,%2,%3};" \
    : "+f"((d)[0]),"+f"((d)[1]),"+f"((d)[2]),"+f"((d)[3]) \
    : "r"((a)[0]),"r"((a)[1]),"r"((a)[2]),"r"((a)[3]),"r"((b)[0]),"r"((b)[1]))

// ---------------- prepass kernels ----------------
__global__ void pool_kernel(const float* __restrict__ in, float* __restrict__ out) {
    int idx = blockIdx.x * blockDim.x + threadIdx.x;
    if (idx >= NIMG*25*784) return;
    int plane = idx / 784, rem = idx % 784;
    int r = rem / 28, c = rem % 28;
    const float* p = in + ((size_t)plane*112 + r*4)*112 + c*4;
    float m = -INFINITY;
#pragma unroll
    for (int i = 0; i < 4; i++)
#pragma unroll
        for (int j = 0; j < 4; j++) m = fmaxf(m, p[i*112+j]);
    out[idx] = m;
}

// features+pooled (NCHW f32) -> g_in [n][pix][hl][576] bf16
__global__ void pack_input(const float* __restrict__ feat, const float* __restrict__ pooled,
                           __nv_bfloat16* __restrict__ out) {
    __shared__ float tile[32][113];
    int pt = blockIdx.x, ct = blockIdx.y, n = blockIdx.z, tid = threadIdx.x;
    for (int idx = tid; idx < 32*112; idx += 256) {
        int cl = idx / 112, pl = idx % 112;
        int c = ct*32 + cl, p = pt*112 + pl;
        float v = 0.f;
        if (c < 512) v = feat[((size_t)n*512 + c)*784 + p];
        else if (c < C1) v = pooled[((size_t)n*25 + (c-512))*784 + p];
        tile[cl][pl] = v;
    }
    __syncthreads();
    for (int idx = tid; idx < 112*32; idx += 256) {
        int pl = idx / 32, cl = idx % 32;
        float v = tile[cl][pl];
        __nv_bfloat16 hi = __float2bfloat16(v);
        __nv_bfloat16 lo = __float2bfloat16(v - __bfloat162float(hi));
        size_t base = ((size_t)n*784 + pt*112 + pl)*2;
        out[(base+0)*576 + ct*32 + cl] = hi;
        out[(base+1)*576 + ct*32 + cl] = lo;
    }
}

// All 4 weight tensors in one launch: [o][c][9] f32 -> [stage][hl][o][64] bf16
__global__ void pack_w_all(const float* __restrict__ w1, const float* __restrict__ w2,
                           const float* __restrict__ w3, const float* __restrict__ w4,
                           __nv_bfloat16* __restrict__ o1, __nv_bfloat16* __restrict__ o2,
                           __nv_bfloat16* __restrict__ o3, __nv_bfloat16* __restrict__ o4) {
    int idx = blockIdx.x * blockDim.x + threadIdx.x;
    const int SZ1 = 81*16384, SZ = 36*16384;
    const float* w; __nv_bfloat16* out; int C, loc;
    if (idx < SZ1)                { w = w1; out = o1; C = C1;  loc = idx; }
    else if (idx < SZ1 + SZ)      { w = w2; out = o2; C = 256; loc = idx - SZ1; }
    else if (idx < SZ1 + 2*SZ)    { w = w3; out = o3; C = 256; loc = idx - SZ1 - SZ; }
    else if (idx < SZ1 + 3*SZ)    { w = w4; out = o4; C = 256; loc = idx - SZ1 - 2*SZ; }
    else return;
    int ch = loc & 63, o = (loc >> 6) & 255, t = (loc >> 14) % 9, chunk = loc / (9*16384);
    int c = chunk*64 + ch;
    float v = (c < C) ? w[((size_t)o*C + c)*9 + t] : 0.f;
    __nv_bfloat16 hi = __float2bfloat16(v);
    __nv_bfloat16 lo = __float2bfloat16(v - __bfloat162float(hi));
    size_t b = (((size_t)(chunk*9+t)*2)*256 + o)*64 + ch;
    out[b] = hi;
    out[b + (size_t)256*64] = lo;
}

// ---------------- main HMMA conv layer ----------------
// D[256 o][112 pix] per CTA; 512 threads, warp grid 8(m) x 2(n): 32o x 56pix per warp.
// Inner loop: ni processed in pairs, MMAs round-robined over 4 accumulators so the
// same accumulator is revisited at distance 4 (>= HMMA latency), not 1.
__global__ __launch_bounds__(512, 1)
void conv_mma(const __nv_bfloat16* __restrict__ actIn, int CpadIn, int nChunks,
              const __nv_bfloat16* __restrict__ wPack,
              __nv_bfloat16* __restrict__ actOut, float* __restrict__ fOut)
{
    extern __shared__ __align__(1024) char smem[];
    uint32_t sb = smem_u32(smem);
    int tid = threadIdx.x, wid = tid >> 5, lane = tid & 31;
    int rt = blockIdx.x, n = blockIdx.z;
    int r0 = rt * 4;
    int wm = wid & 7, wn = wid >> 3;        // warp tile: 32 o x 56 pix

    const int nStages = nChunks * 9;

    float d[2][7][4];
#pragma unroll
    for (int mi = 0; mi < 2; mi++)
#pragma unroll
        for (int ni = 0; ni < 7; ni++)
#pragma unroll
            for (int k = 0; k < 4; k++) d[mi][ni][k] = 0.f;

    auto fill = [&](int s, int buf) {
        int chunk = s / 9, t = s - chunk*9;
        int dh = c_dh[t], dw = c_dw[t];
        const __nv_bfloat16* wS = wPack + (size_t)s*2*256*64;
#pragma unroll 1
        for (int u = tid; u < 5888; u += 512) {
            if (u < 4096) {            // A: weights, 256 rows x 2 hl x 8 segs
                int o = u >> 4, rem = u & 15, hl = rem >> 3, seg = rem & 7;
                const void* src = wS + (((size_t)hl*256) + o)*64 + seg*8;
                uint32_t bo = (o << 7) + (seg << 4);
                cpa(sb + ASM(buf,hl) + SWZ(bo), src, 16);
            } else {                   // B: tap-shifted pixels, 112 rows x 2 hl x 8 segs
                int v = u - 4096;
                int i = v >> 4, rem = v & 15, hl = rem >> 3, seg = rem & 7;
                int ri = i / 28;
                int rr = r0 + ri + dh, cc = (i - ri*28) + dw;
                bool ok = ((unsigned)rr < 28u) && ((unsigned)cc < 28u);
                const void* src = actIn +
                    (((size_t)n*784 + (ok ? rr*28 + cc : 0))*2 + hl)*CpadIn + chunk*64 + seg*8;
                uint32_t bo = (i << 7) + (seg << 4);
                cpa(sb + BSM(buf,hl) + SWZ(bo), src, ok ? 16 : 0);
            }
        }
    };

    int aRow  = (lane & 15);
    int aColb = (lane >> 4) << 4;
    int bRow  = (lane & 7);
    int bColb = ((lane >> 3) & 1) << 4;

    fill(0, 0); CP_COMMIT();

    for (int s = 0; s < nStages; s++) {
        int buf = s & 1;
        if (s + 1 < nStages) { fill(s+1, buf ^ 1); CP_COMMIT(); CP_WAIT1(); }
        else CP_WAIT0();
        __syncthreads();

#pragma unroll
        for (int ks = 0; ks < 4; ks++) {
            uint32_t ah[2][4], al[2][4];
#pragma unroll
            for (int mi = 0; mi < 2; mi++) {
                uint32_t ro = (wm*32 + mi*16 + aRow) << 7;
                uint32_t co = ks*32 + aColb;
                LDSM4(ah[mi], sb + ASM(buf,0) + SWZ(ro + co));
                LDSM4(al[mi], sb + ASM(buf,1) + SWZ(ro + co));
            }
            // ni pairs: 12 MMAs round-robin over 4 accumulators (reuse distance 4)
#pragma unroll
            for (int np = 0; np < 6; np += 2) {
                uint32_t co = ks*32 + bColb;
                uint32_t ro0 = (wn*56 + np*8 + bRow) << 7;
                uint32_t ro1 = (wn*56 + (np+1)*8 + bRow) << 7;
                uint32_t bh0[2], bl0[2], bh1[2], bl1[2];
                LDSM2(bh0, sb + BSM(buf,0) + SWZ(ro0 + co));
                LDSM2(bl0, sb + BSM(buf,1) + SWZ(ro0 + co));
                LDSM2(bh1, sb + BSM(buf,0) + SWZ(ro1 + co));
                LDSM2(bl1, sb + BSM(buf,1) + SWZ(ro1 + co));
                MMA(d[0][np],   ah[0], bh0);
                MMA(d[1][np],   ah[1], bh0);
                MMA(d[0][np+1], ah[0], bh1);
                MMA(d[1][np+1], ah[1], bh1);
                MMA(d[0][np],   ah[0], bl0);
                MMA(d[1][np],   ah[1], bl0);
                MMA(d[0][np+1], ah[0], bl1);
                MMA(d[1][np+1], ah[1], bl1);
                MMA(d[0][np],   al[0], bh0);
                MMA(d[1][np],   al[1], bh0);
                MMA(d[0][np+1], al[0], bh1);
                MMA(d[1][np+1], al[1], bh1);
            }
            {   // ni = 6 (distance 2)
                uint32_t co = ks*32 + bColb;
                uint32_t ro = (wn*56 + 48 + bRow) << 7;
                uint32_t bh[2], bl[2];
                LDSM2(bh, sb + BSM(buf,0) + SWZ(ro + co));
                LDSM2(bl, sb + BSM(buf,1) + SWZ(ro + co));
                MMA(d[0][6], ah[0], bh);
                MMA(d[1][6], ah[1], bh);
                MMA(d[0][6], ah[0], bl);
                MMA(d[1][6], ah[1], bl);
                MMA(d[0][6], al[0], bh);
                MMA(d[1][6], al[1], bh);
            }
        }
        __syncthreads();
    }

    // ---- epilogue: ReLU + store ----
    int quad = lane >> 2, four = lane & 3;
#pragma unroll
    for (int mi = 0; mi < 2; mi++)
#pragma unroll
        for (int ni = 0; ni < 7; ni++)
#pragma unroll
            for (int k = 0; k < 4; k++) {
                float v = fmaxf(d[mi][ni][k], 0.f);
                int o   = wm*32 + mi*16 + quad + ((k >> 1) << 3);
                int pix = rt*112 + wn*56 + ni*8 + four*2 + (k & 1);
                if (actOut) {
                    __nv_bfloat16 hi = __float2bfloat16(v);
                    __nv_bfloat16 lo = __float2bfloat16(v - __bfloat162float(hi));
                    size_t b = ((size_t)n*784 + pix)*2;
                    actOut[(b+0)*256 + o] = hi;
                    actOut[(b+1)*256 + o] = lo;
                } else {
                    fOut[((size_t)n*256 + o)*784 + pix] = v;
                }
            }
}

// ---------------------------------------------------------------------------
extern "C" void kernel_launch(void* const* d_in, const int* in_sizes, int n_in,
                              void* d_out, int out_size)
{
    const float* features  = (const float*)d_in[0];
    const float* fine_segm = (const float*)d_in[1];
    const float* w1 = (const float*)d_in[2];
    const float* w2 = (const float*)d_in[3];
    const float* w3 = (const float*)d_in[4];
    const float* w4 = (const float*)d_in[5];
    float* out = (float*)d_out;

    float *pooled; __nv_bfloat16 *in, *yA, *yB, *w1p, *w2p, *w3p, *w4p;
    cudaGetSymbolAddress((void**)&pooled, g_pooled);
    cudaGetSymbolAddress((void**)&in,  g_in);
    cudaGetSymbolAddress((void**)&yA,  g_yA);
    cudaGetSymbolAddress((void**)&yB,  g_yB);
    cudaGetSymbolAddress((void**)&w1p, g_w1p);
    cudaGetSymbolAddress((void**)&w2p, g_w2p);
    cudaGetSymbolAddress((void**)&w3p, g_w3p);
    cudaGetSymbolAddress((void**)&w4p, g_w4p);

    cudaFuncSetAttribute(conv_mma, cudaFuncAttributeMaxDynamicSharedMemorySize, SMEMSZ);

    pool_kernel<<<(NIMG*25*784 + 255)/256, 256>>>(fine_segm, pooled);
    pack_input<<<dim3(7,18,NIMG), 256>>>(features, pooled, in);
    {
        int total = (81 + 3*36) * 16384;
        pack_w_all<<<(total + 255)/256, 256>>>(w1, w2, w3, w4, w1p, w2p, w3p, w4p);
    }

    dim3 grid(7, 1, NIMG);
    conv_mma<<<grid, 512, SMEMSZ>>>(in, 576, 9, w1p, yA, nullptr);
    conv_mma<<<grid, 512, SMEMSZ>>>(yA, 256, 4, w2p, yB, nullptr);
    conv_mma<<<grid, 512, SMEMSZ>>>(yB, 256, 4, w3p, yA, nullptr);
    conv_mma<<<grid, 512, SMEMSZ>>>(yA, 256, 4, w4p, nullptr, out);
}

// round 13
// speedup vs baseline: 1.9104x; 1.9104x over previous
#include <cuda_runtime.h>
#include <cuda_bf16.h>
#include <cstdint>
#include <math.h>

#define NIMG 128
#define OCH 256
#define C1 537

// SMEM: double-buffered stage = A(2x32KB hi/lo) + B(2x14KB hi/lo) = 94208 B
#define STG 94208
#define ASMO(b,hl) ((b)*STG + (hl)*32768)           // A: 256 rows x 128B
#define BSMO(b,hl) ((b)*STG + 65536 + (hl)*14336)   // B: 112 rows x 128B
#define SMEMSZ (2*STG)                              // 188416 B
#define SWZ(x) ((x) ^ (((x)>>3)&0x70))

__device__ __constant__ int c_dh[9] = {-1,-1,-1,0,0,-2,0,2,3};
__device__ __constant__ int c_dw[9] = {-3,-1,1,0,2,1,-1,0,1};

__device__ __align__(128) float         g_pooled[(size_t)NIMG*25*784];
__device__ __align__(128) __nv_bfloat16 g_in [(size_t)NIMG*784*2*576];
__device__ __align__(128) __nv_bfloat16 g_yA [(size_t)NIMG*784*2*256];
__device__ __align__(128) __nv_bfloat16 g_yB [(size_t)NIMG*784*2*256];
__device__ __align__(128) __nv_bfloat16 g_w1p[(size_t)81*2*256*64];
__device__ __align__(128) __nv_bfloat16 g_w2p[(size_t)36*2*256*64];
__device__ __align__(128) __nv_bfloat16 g_w3p[(size_t)36*2*256*64];
__device__ __align__(128) __nv_bfloat16 g_w4p[(size_t)36*2*256*64];

__device__ __forceinline__ uint32_t smem_u32(const void* p) {
    uint32_t a;
    asm("{ .reg .u64 t; cvta.to.shared.u64 t, %1; cvt.u32.u64 %0, t; }" : "=r"(a) : "l"(p));
    return a;
}
__device__ __forceinline__ void cpa(uint32_t dst, const void* src, uint32_t sz) {
    asm volatile("cp.async.cg.shared.global [%0], [%1], 16, %2;" :: "r"(dst), "l"(src), "r"(sz));
}
#define CP_COMMIT() asm volatile("cp.async.commit_group;" ::: "memory")
#define CP_WAIT0()  asm volatile("cp.async.wait_group 0;" ::: "memory")
#define LDSM4(r,a) asm volatile("ldmatrix.sync.aligned.m8n8.x4.shared.b16 {%0,%1,%2,%3}, [%4];" \
    : "=r"((r)[0]),"=r"((r)[1]),"=r"((r)[2]),"=r"((r)[3]) : "r"(a))
#define LDSM2(r,a) asm volatile("ldmatrix.sync.aligned.m8n8.x2.shared.b16 {%0,%1}, [%2];" \
    : "=r"((r)[0]),"=r"((r)[1]) : "r"(a))
#define MMA(d,a,b) asm volatile( \
    "mma.sync.aligned.m16n8k16.row.col.f32.bf16.bf16.f32 {%0,%1,%2,%3}, {%4,%5,%6,%7}, {%8,%9}, {%0,%1,%2,%3};" \
    : "+f"((d)[0]),"+f"((d)[1]),"+f"((d)[2]),"+f"((d)[3]) \
    : "r"((a)[0]),"r"((a)[1]),"r"((a)[2]),"r"((a)[3]),"r"((b)[0]),"r"((b)[1]))

// ---------------- prepass kernels ----------------
__global__ void pool_kernel(const float* __restrict__ in, float* __restrict__ out) {
    int idx = blockIdx.x * blockDim.x + threadIdx.x;
    if (idx >= NIMG*25*784) return;
    int plane = idx / 784, rem = idx % 784;
    int r = rem / 28, c = rem % 28;
    const float* p = in + ((size_t)plane*112 + r*4)*112 + c*4;
    float m = -INFINITY;
#pragma unroll
    for (int i = 0; i < 4; i++)
#pragma unroll
        for (int j = 0; j < 4; j++) m = fmaxf(m, p[i*112+j]);
    out[idx] = m;
}

// features+pooled (NCHW f32) -> g_in [n][pix][hl][576] bf16
__global__ void pack_input(const float* __restrict__ feat, const float* __restrict__ pooled,
                           __nv_bfloat16* __restrict__ out) {
    __shared__ float tile[32][113];
    int pt = blockIdx.x, ct = blockIdx.y, n = blockIdx.z, tid = threadIdx.x;
    for (int idx = tid; idx < 32*112; idx += 256) {
        int cl = idx / 112, pl = idx % 112;
        int c = ct*32 + cl, p = pt*112 + pl;
        float v = 0.f;
        if (c < 512) v = feat[((size_t)n*512 + c)*784 + p];
        else if (c < C1) v = pooled[((size_t)n*25 + (c-512))*784 + p];
        tile[cl][pl] = v;
    }
    __syncthreads();
    for (int idx = tid; idx < 112*32; idx += 256) {
        int pl = idx / 32, cl = idx % 32;
        float v = tile[cl][pl];
        __nv_bfloat16 hi = __float2bfloat16(v);
        __nv_bfloat16 lo = __float2bfloat16(v - __bfloat162float(hi));
        size_t base = ((size_t)n*784 + pt*112 + pl)*2;
        out[(base+0)*576 + ct*32 + cl] = hi;
        out[(base+1)*576 + ct*32 + cl] = lo;
    }
}

// All 4 weight tensors in one launch: [o][c][9] f32 -> [stage][hl][o][64] bf16
__global__ void pack_w_all(const float* __restrict__ w1, const float* __restrict__ w2,
                           const float* __restrict__ w3, const float* __restrict__ w4,
                           __nv_bfloat16* __restrict__ o1, __nv_bfloat16* __restrict__ o2,
                           __nv_bfloat16* __restrict__ o3, __nv_bfloat16* __restrict__ o4) {
    int idx = blockIdx.x * blockDim.x + threadIdx.x;
    const int SZ1 = 81*16384, SZ = 36*16384;
    const float* w; __nv_bfloat16* out; int C, loc;
    if (idx < SZ1)                { w = w1; out = o1; C = C1;  loc = idx; }
    else if (idx < SZ1 + SZ)      { w = w2; out = o2; C = 256; loc = idx - SZ1; }
    else if (idx < SZ1 + 2*SZ)    { w = w3; out = o3; C = 256; loc = idx - SZ1 - SZ; }
    else if (idx < SZ1 + 3*SZ)    { w = w4; out = o4; C = 256; loc = idx - SZ1 - 2*SZ; }
    else return;
    int ch = loc & 63, o = (loc >> 6) & 255, t = (loc >> 14) % 9, chunk = loc / (9*16384);
    int c = chunk*64 + ch;
    float v = (c < C) ? w[((size_t)o*C + c)*9 + t] : 0.f;
    __nv_bfloat16 hi = __float2bfloat16(v);
    __nv_bfloat16 lo = __float2bfloat16(v - __bfloat162float(hi));
    size_t b = (((size_t)(chunk*9+t)*2)*256 + o)*64 + ch;
    out[b] = hi;
    out[b + (size_t)256*64] = lo;
}

// ---------------- main HMMA conv layer ----------------
// D[256 o][112 pix] per CTA; 512 threads, warp grid 8(m) x 2(n): 32o x 56pix per warp.
// One __syncthreads per stage; fill addressing hoisted out of the stage loop.
__global__ __launch_bounds__(512, 1)
void conv_mma(const __nv_bfloat16* __restrict__ actIn, int CpadIn, int nChunks,
              const __nv_bfloat16* __restrict__ wPack,
              __nv_bfloat16* __restrict__ actOut, float* __restrict__ fOut)
{
    extern __shared__ __align__(1024) char smem[];
    uint32_t sb = smem_u32(smem);
    int tid = threadIdx.x, wid = tid >> 5, lane = tid & 31;
    int rt = blockIdx.x, n = blockIdx.z;
    int r0 = rt * 4;
    int wm = wid & 7, wn = wid >> 3;        // warp tile: 32 o x 56 pix

    const int nStages = nChunks * 9;

    // ---- hoisted fill addressing (invariant across stages) ----
    const int fseg = tid & 7;               // 16B segment within 128B row
    const int fhl  = (tid >> 3) & 1;        // hi/lo limb plane
    const int frow0 = tid >> 4;             // row for k=0 (A) / slot m=0 (B)
    // A: 8 copies, row(k) = frow0 + 32k; src stride 4096 B, dst stride 4096 B (swizzle-safe)
    const __nv_bfloat16* aSrc0 = wPack + (size_t)fhl*16384 + frow0*64 + fseg*8;
    const uint32_t aDst0 = SWZ((uint32_t)(frow0*128 + fseg*16));
    // B: slots m=0..nB-1, i(m) = frow0 + 32m; one-time div/mod
    const int nB = (tid < 256) ? 4 : 3;
    int bRi[4], bCi[4];
#pragma unroll
    for (int m = 0; m < 4; m++) { int i = frow0 + 32*m; bRi[m] = i / 28; bCi[m] = i - (i/28)*28; }
    const uint32_t bDst0 = SWZ((uint32_t)(frow0*128 + fseg*16));
    const __nv_bfloat16* bSrcN = actIn + (size_t)n*784*2*CpadIn + (size_t)fhl*CpadIn + fseg*8;

    float d[2][7][4];
#pragma unroll
    for (int mi = 0; mi < 2; mi++)
#pragma unroll
        for (int ni = 0; ni < 7; ni++)
#pragma unroll
            for (int k = 0; k < 4; k++) d[mi][ni][k] = 0.f;

    auto fill = [&](int s, int buf) {
        int chunk = s / 9, t = s - chunk*9;
        int dh = c_dh[t], dw = c_dw[t];
        const __nv_bfloat16* aS = aSrc0 + (size_t)s*2*256*64;
        uint32_t aD = sb + ASMO(buf,fhl) + aDst0;
#pragma unroll
        for (int k = 0; k < 8; k++)
            cpa(aD + 4096u*k, aS + 2048*k, 16);
        const __nv_bfloat16* bS = bSrcN + chunk*64;
        uint32_t bD = sb + BSMO(buf,fhl) + bDst0;
#pragma unroll
        for (int m = 0; m < 4; m++) {
            if (m == 3 && nB == 3) break;
            int rr = r0 + bRi[m] + dh, cc = bCi[m] + dw;
            bool ok = ((unsigned)rr < 28u) && ((unsigned)cc < 28u);
            const void* src = bS + (size_t)(ok ? (rr*28 + cc) : 0) * 2 * CpadIn;
            cpa(bD + 4096u*m, src, ok ? 16 : 0);
        }
    };

    int aRow  = (lane & 15);
    int aColb = (lane >> 4) << 4;
    int bRow  = (lane & 7);
    int bColb = ((lane >> 3) & 1) << 4;

    fill(0, 0); CP_COMMIT();

    for (int s = 0; s < nStages; s++) {
        int buf = s & 1;
        CP_WAIT0();
        __syncthreads();   // single barrier: orders fill(s) visibility AND compute(s-1) vs fill(s+1)
        if (s + 1 < nStages) { fill(s+1, buf ^ 1); CP_COMMIT(); }

#pragma unroll
        for (int ks = 0; ks < 4; ks++) {
            uint32_t ah[2][4], al[2][4];
#pragma unroll
            for (int mi = 0; mi < 2; mi++) {
                uint32_t ro = (wm*32 + mi*16 + aRow) << 7;
                uint32_t co = ks*32 + aColb;
                LDSM4(ah[mi], sb + ASMO(buf,0) + SWZ(ro + co));
                LDSM4(al[mi], sb + ASMO(buf,1) + SWZ(ro + co));
            }
#pragma unroll
            for (int ni = 0; ni < 7; ni++) {
                uint32_t ro = (wn*56 + ni*8 + bRow) << 7;
                uint32_t co = ks*32 + bColb;
                uint32_t bh[2], bl[2];
                LDSM2(bh, sb + BSMO(buf,0) + SWZ(ro + co));
                LDSM2(bl, sb + BSMO(buf,1) + SWZ(ro + co));
#pragma unroll
                for (int mi = 0; mi < 2; mi++) {
                    MMA(d[mi][ni], ah[mi], bh);
                    MMA(d[mi][ni], ah[mi], bl);
                    MMA(d[mi][ni], al[mi], bh);
                }
            }
        }
    }

    // ---- epilogue: ReLU + store ----
    int quad = lane >> 2, four = lane & 3;
#pragma unroll
    for (int mi = 0; mi < 2; mi++)
#pragma unroll
        for (int ni = 0; ni < 7; ni++)
#pragma unroll
            for (int k = 0; k < 4; k++) {
                float v = fmaxf(d[mi][ni][k], 0.f);
                int o   = wm*32 + mi*16 + quad + ((k >> 1) << 3);
                int pix = rt*112 + wn*56 + ni*8 + four*2 + (k & 1);
                if (actOut) {
                    __nv_bfloat16 hi = __float2bfloat16(v);
                    __nv_bfloat16 lo = __float2bfloat16(v - __bfloat162float(hi));
                    size_t b = ((size_t)n*784 + pix)*2;
                    actOut[(b+0)*256 + o] = hi;
                    actOut[(b+1)*256 + o] = lo;
                } else {
                    fOut[((size_t)n*256 + o)*784 + pix] = v;
                }
            }
}

// ---------------------------------------------------------------------------
extern "C" void kernel_launch(void* const* d_in, const int* in_sizes, int n_in,
                              void* d_out, int out_size)
{
    const float* features  = (const float*)d_in[0];
    const float* fine_segm = (const float*)d_in[1];
    const float* w1 = (const float*)d_in[2];
    const float* w2 = (const float*)d_in[3];
    const float* w3 = (const float*)d_in[4];
    const float* w4 = (const float*)d_in[5];
    float* out = (float*)d_out;

    float *pooled; __nv_bfloat16 *in, *yA, *yB, *w1p, *w2p, *w3p, *w4p;
    cudaGetSymbolAddress((void**)&pooled, g_pooled);
    cudaGetSymbolAddress((void**)&in,  g_in);
    cudaGetSymbolAddress((void**)&yA,  g_yA);
    cudaGetSymbolAddress((void**)&yB,  g_yB);
    cudaGetSymbolAddress((void**)&w1p, g_w1p);
    cudaGetSymbolAddress((void**)&w2p, g_w2p);
    cudaGetSymbolAddress((void**)&w3p, g_w3p);
    cudaGetSymbolAddress((void**)&w4p, g_w4p);

    cudaFuncSetAttribute(conv_mma, cudaFuncAttributeMaxDynamicSharedMemorySize, SMEMSZ);

    pool_kernel<<<(NIMG*25*784 + 255)/256, 256>>>(fine_segm, pooled);
    pack_input<<<dim3(7,18,NIMG), 256>>>(features, pooled, in);
    {
        int total = (81 + 3*36) * 16384;
        pack_w_all<<<(total + 255)/256, 256>>>(w1, w2, w3, w4, w1p, w2p, w3p, w4p);
    }

    dim3 grid(7, 1, NIMG);
    conv_mma<<<grid, 512, SMEMSZ>>>(in, 576, 9, w1p, yA, nullptr);
    conv_mma<<<grid, 512, SMEMSZ>>>(yA, 256, 4, w2p, yB, nullptr);
    conv_mma<<<grid, 512, SMEMSZ>>>(yB, 256, 4, w3p, yA, nullptr);
    conv_mma<<<grid, 512, SMEMSZ>>>(yA, 256, 4, w4p, nullptr, out);
}

// round 14
// speedup vs baseline: 2.6386x; 1.3812x over previous
#include <cuda_runtime.h>
#include <cuda_fp16.h>
#include <cstdint>
#include <math.h>

#define NIMG 128
#define OCH 256
#define C1 537

// SMEM: double-buffered stage = A(16KB, single fp16 plane) + B(2x14KB xh/xl) = 45056 B
#define STG 45056
#define ASMO(b)     ((b)*STG)                       // A: 128 rows x 128B
#define BSMO(b,hl)  ((b)*STG + 16384 + (hl)*14336)  // B: 112 rows x 128B
#define SMEMSZ (2*STG)                              // 90112 B -> 2 CTAs/SM
#define SWZ(x) ((x) ^ (((x)>>3)&0x70))

__device__ __constant__ int c_dh[9] = {-1,-1,-1,0,0,-2,0,2,3};
__device__ __constant__ int c_dw[9] = {-3,-1,1,0,2,1,-1,0,1};

__device__ __align__(128) float  g_pooled[(size_t)NIMG*25*784];
__device__ __align__(128) __half g_in [(size_t)NIMG*784*2*576];
__device__ __align__(128) __half g_yA [(size_t)NIMG*784*2*256];
__device__ __align__(128) __half g_yB [(size_t)NIMG*784*2*256];
__device__ __align__(128) __half g_w1p[(size_t)81*256*64];
__device__ __align__(128) __half g_w2p[(size_t)36*256*64];
__device__ __align__(128) __half g_w3p[(size_t)36*256*64];
__device__ __align__(128) __half g_w4p[(size_t)36*256*64];

__device__ __forceinline__ uint32_t smem_u32(const void* p) {
    uint32_t a;
    asm("{ .reg .u64 t; cvta.to.shared.u64 t, %1; cvt.u32.u64 %0, t; }" : "=r"(a) : "l"(p));
    return a;
}
__device__ __forceinline__ void cpa(uint32_t dst, const void* src, uint32_t sz) {
    asm volatile("cp.async.cg.shared.global [%0], [%1], 16, %2;" :: "r"(dst), "l"(src), "r"(sz));
}
#define CP_COMMIT() asm volatile("cp.async.commit_group;" ::: "memory")
#define CP_WAIT0()  asm volatile("cp.async.wait_group 0;" ::: "memory")
#define LDSM4(r,a) asm volatile("ldmatrix.sync.aligned.m8n8.x4.shared.b16 {%0,%1,%2,%3}, [%4];" \
    : "=r"((r)[0]),"=r"((r)[1]),"=r"((r)[2]),"=r"((r)[3]) : "r"(a))
#define LDSM2(r,a) asm volatile("ldmatrix.sync.aligned.m8n8.x2.shared.b16 {%0,%1}, [%2];" \
    : "=r"((r)[0]),"=r"((r)[1]) : "r"(a))
#define MMA(d,a,b) asm volatile( \
    "mma.sync.aligned.m16n8k16.row.col.f32.f16.f16.f32 {%0,%1,%2,%3}, {%4,%5,%6,%7}, {%8,%9}, {%0,%1,%2,%3};" \
    : "+f"((d)[0]),"+f"((d)[1]),"+f"((d)[2]),"+f"((d)[3]) \
    : "r"((a)[0]),"r"((a)[1]),"r"((a)[2]),"r"((a)[3]),"r"((b)[0]),"r"((b)[1]))

// ---------------- prepass kernels ----------------
__global__ void pool_kernel(const float* __restrict__ in, float* __restrict__ out) {
    int idx = blockIdx.x * blockDim.x + threadIdx.x;
    if (idx >= NIMG*25*784) return;
    int plane = idx / 784, rem = idx % 784;
    int r = rem / 28, c = rem % 28;
    const float* p = in + ((size_t)plane*112 + r*4)*112 + c*4;
    float m = -INFINITY;
#pragma unroll
    for (int i = 0; i < 4; i++)
#pragma unroll
        for (int j = 0; j < 4; j++) m = fmaxf(m, p[i*112+j]);
    out[idx] = m;
}

// features+pooled (NCHW f32) -> g_in [n][pix][hl][576] fp16 (hl: xh, xl residual)
__global__ void pack_input(const float* __restrict__ feat, const float* __restrict__ pooled,
                           __half* __restrict__ out) {
    __shared__ float tile[32][113];
    int pt = blockIdx.x, ct = blockIdx.y, n = blockIdx.z, tid = threadIdx.x;
    for (int idx = tid; idx < 32*112; idx += 256) {
        int cl = idx / 112, pl = idx % 112;
        int c = ct*32 + cl, p = pt*112 + pl;
        float v = 0.f;
        if (c < 512) v = feat[((size_t)n*512 + c)*784 + p];
        else if (c < C1) v = pooled[((size_t)n*25 + (c-512))*784 + p];
        tile[cl][pl] = v;
    }
    __syncthreads();
    for (int idx = tid; idx < 112*32; idx += 256) {
        int pl = idx / 32, cl = idx % 32;
        float v = tile[cl][pl];
        __half hi = __float2half(v);
        __half lo = __float2half(v - __half2float(hi));
        size_t base = ((size_t)n*784 + pt*112 + pl)*2;
        out[(base+0)*576 + ct*32 + cl] = hi;
        out[(base+1)*576 + ct*32 + cl] = lo;
    }
}

// All 4 weight tensors: [o][c][9] f32 -> [stage][o][64] fp16 (single plane)
__global__ void pack_w_all(const float* __restrict__ w1, const float* __restrict__ w2,
                           const float* __restrict__ w3, const float* __restrict__ w4,
                           __half* __restrict__ o1, __half* __restrict__ o2,
                           __half* __restrict__ o3, __half* __restrict__ o4) {
    int idx = blockIdx.x * blockDim.x + threadIdx.x;
    const int SZ1 = 81*16384, SZ = 36*16384;
    const float* w; __half* out; int C, loc;
    if (idx < SZ1)                { w = w1; out = o1; C = C1;  loc = idx; }
    else if (idx < SZ1 + SZ)      { w = w2; out = o2; C = 256; loc = idx - SZ1; }
    else if (idx < SZ1 + 2*SZ)    { w = w3; out = o3; C = 256; loc = idx - SZ1 - SZ; }
    else if (idx < SZ1 + 3*SZ)    { w = w4; out = o4; C = 256; loc = idx - SZ1 - 2*SZ; }
    else return;
    int ch = loc & 63, o = (loc >> 6) & 255, t = (loc >> 14) % 9, chunk = loc / (9*16384);
    int c = chunk*64 + ch;
    float v = (c < C) ? w[((size_t)o*C + c)*9 + t] : 0.f;
    out[((size_t)(chunk*9+t)*256 + o)*64 + ch] = __float2half(v);
}

// ---------------- main HMMA conv layer (fp16 2-term) ----------------
// D[128 o][112 pix] per CTA; 256 threads, warp grid 4(m) x 2(n): 32o x 56pix per warp.
// y = xh*w + xl*w  (x split to fp16 pair, w rounded to fp16). 2 MMAs per k-chunk.
// 2 CTAs resident per SM (90KB smem each) overlap stage-boundary bubbles.
__global__ __launch_bounds__(256, 2)
void conv_mma(const __half* __restrict__ actIn, int CpadIn, int nChunks,
              const __half* __restrict__ wPack,
              __half* __restrict__ actOut, float* __restrict__ fOut)
{
    extern __shared__ __align__(1024) char smem[];
    uint32_t sb = smem_u32(smem);
    int tid = threadIdx.x, wid = tid >> 5, lane = tid & 31;
    int rt = blockIdx.x, oBase = blockIdx.y * 128, n = blockIdx.z;
    int r0 = rt * 4;
    int wm = wid & 3, wn = wid >> 2;        // warp tile: 32 o x 56 pix

    const int nStages = nChunks * 9;

    // ---- hoisted fill addressing ----
    const int fseg = tid & 7;
    // A: 128 rows x 8 segs = 1024 copies / 256 thr = 4 each; rows afrow0 + 32k
    const int afrow0 = tid >> 3;            // 0..31
    const __half* aSrc0 = wPack + ((size_t)oBase + afrow0)*64 + fseg*8;
    const uint32_t aDst0 = SWZ((uint32_t)(afrow0*128 + fseg*16));
    // B: 112 rows x 2 hl x 8 segs = 1792 copies / 256 = 7 each; rows bfrow0 + 16m
    const int bhl = (tid >> 3) & 1;
    const int bfrow0 = tid >> 4;            // 0..15
    int bRi[7], bCi[7];
#pragma unroll
    for (int m = 0; m < 7; m++) { int i = bfrow0 + 16*m; bRi[m] = i / 28; bCi[m] = i - (i/28)*28; }
    const uint32_t bDst0 = SWZ((uint32_t)(bfrow0*128 + fseg*16));
    const __half* bSrcN = actIn + (size_t)n*784*2*CpadIn + (size_t)bhl*CpadIn + fseg*8;

    float d[2][7][4];
#pragma unroll
    for (int mi = 0; mi < 2; mi++)
#pragma unroll
        for (int ni = 0; ni < 7; ni++)
#pragma unroll
            for (int k = 0; k < 4; k++) d[mi][ni][k] = 0.f;

    auto fill = [&](int s, int buf) {
        int chunk = s / 9, t = s - chunk*9;
        int dh = c_dh[t], dw = c_dw[t];
        const __half* aS = aSrc0 + (size_t)s*256*64;
        uint32_t aD = sb + ASMO(buf) + aDst0;
#pragma unroll
        for (int k = 0; k < 4; k++)
            cpa(aD + 4096u*k, aS + 2048*k, 16);
        const __half* bS = bSrcN + chunk*64;
        uint32_t bD = sb + BSMO(buf,bhl) + bDst0;
#pragma unroll
        for (int m = 0; m < 7; m++) {
            int rr = r0 + bRi[m] + dh, cc = bCi[m] + dw;
            bool ok = ((unsigned)rr < 28u) && ((unsigned)cc < 28u);
            const void* src = bS + (size_t)(ok ? (rr*28 + cc) : 0) * 2 * CpadIn;
            cpa(bD + 2048u*m, src, ok ? 16 : 0);
        }
    };

    int aRow  = (lane & 15);
    int aColb = (lane >> 4) << 4;
    int bRow  = (lane & 7);
    int bColb = ((lane >> 3) & 1) << 4;

    fill(0, 0); CP_COMMIT();

    for (int s = 0; s < nStages; s++) {
        int buf = s & 1;
        CP_WAIT0();
        __syncthreads();   // orders fill(s) visibility AND compute(s-1) vs fill(s+1)
        if (s + 1 < nStages) { fill(s+1, buf ^ 1); CP_COMMIT(); }

#pragma unroll
        for (int ks = 0; ks < 4; ks++) {
            uint32_t a[2][4];
#pragma unroll
            for (int mi = 0; mi < 2; mi++) {
                uint32_t ro = (wm*32 + mi*16 + aRow) << 7;
                uint32_t co = ks*32 + aColb;
                LDSM4(a[mi], sb + ASMO(buf) + SWZ(ro + co));
            }
#pragma unroll
            for (int ni = 0; ni < 7; ni++) {
                uint32_t ro = (wn*56 + ni*8 + bRow) << 7;
                uint32_t co = ks*32 + bColb;
                uint32_t bh[2], bl[2];
                LDSM2(bh, sb + BSMO(buf,0) + SWZ(ro + co));
                LDSM2(bl, sb + BSMO(buf,1) + SWZ(ro + co));
                MMA(d[0][ni], a[0], bh);
                MMA(d[1][ni], a[1], bh);
                MMA(d[0][ni], a[0], bl);
                MMA(d[1][ni], a[1], bl);
            }
        }
    }

    // ---- epilogue: ReLU + store ----
    int quad = lane >> 2, four = lane & 3;
#pragma unroll
    for (int mi = 0; mi < 2; mi++)
#pragma unroll
        for (int ni = 0; ni < 7; ni++)
#pragma unroll
            for (int k = 0; k < 4; k++) {
                float v = fmaxf(d[mi][ni][k], 0.f);
                int o   = oBase + wm*32 + mi*16 + quad + ((k >> 1) << 3);
                int pix = rt*112 + wn*56 + ni*8 + four*2 + (k & 1);
                if (actOut) {
                    __half hi = __float2half(v);
                    __half lo = __float2half(v - __half2float(hi));
                    size_t b = ((size_t)n*784 + pix)*2;
                    actOut[(b+0)*256 + o] = hi;
                    actOut[(b+1)*256 + o] = lo;
                } else {
                    fOut[((size_t)n*256 + o)*784 + pix] = v;
                }
            }
}

// ---------------------------------------------------------------------------
extern "C" void kernel_launch(void* const* d_in, const int* in_sizes, int n_in,
                              void* d_out, int out_size)
{
    const float* features  = (const float*)d_in[0];
    const float* fine_segm = (const float*)d_in[1];
    const float* w1 = (const float*)d_in[2];
    const float* w2 = (const float*)d_in[3];
    const float* w3 = (const float*)d_in[4];
    const float* w4 = (const float*)d_in[5];
    float* out = (float*)d_out;

    float *pooled; __half *in, *yA, *yB, *w1p, *w2p, *w3p, *w4p;
    cudaGetSymbolAddress((void**)&pooled, g_pooled);
    cudaGetSymbolAddress((void**)&in,  g_in);
    cudaGetSymbolAddress((void**)&yA,  g_yA);
    cudaGetSymbolAddress((void**)&yB,  g_yB);
    cudaGetSymbolAddress((void**)&w1p, g_w1p);
    cudaGetSymbolAddress((void**)&w2p, g_w2p);
    cudaGetSymbolAddress((void**)&w3p, g_w3p);
    cudaGetSymbolAddress((void**)&w4p, g_w4p);

    cudaFuncSetAttribute(conv_mma, cudaFuncAttributeMaxDynamicSharedMemorySize, SMEMSZ);

    pool_kernel<<<(NIMG*25*784 + 255)/256, 256>>>(fine_segm, pooled);
    pack_input<<<dim3(7,18,NIMG), 256>>>(features, pooled, in);
    {
        int total = (81 + 3*36) * 16384;
        pack_w_all<<<(total + 255)/256, 256>>>(w1, w2, w3, w4, w1p, w2p, w3p, w4p);
    }

    dim3 grid(7, 2, NIMG);   // 7 pix tiles x 2 o-halves x 128 images = 1792 CTAs
    conv_mma<<<grid, 256, SMEMSZ>>>(in, 576, 9, w1p, yA, nullptr);
    conv_mma<<<grid, 256, SMEMSZ>>>(yA, 256, 4, w2p, yB, nullptr);
    conv_mma<<<grid, 256, SMEMSZ>>>(yB, 256, 4, w3p, yA, nullptr);
    conv_mma<<<grid, 256, SMEMSZ>>>(yA, 256, 4, w4p, nullptr, out);
}

// round 15
// speedup vs baseline: 3.4140x; 1.2939x over previous
#include <cuda_runtime.h>
#include <cuda_fp16.h>
#include <cstdint>
#include <math.h>

#define NIMG 128
#define OCH 256
#define C1 537

// SMEM: double-buffered stage = A(16KB fp16 weights) + B(14KB fp16 pixels) = 30720 B
#define STG 30720
#define ASMO(b)  ((b)*STG)                   // A: 128 rows x 128B
#define BSMO(b)  ((b)*STG + 16384)           // B: 112 rows x 128B
#define SMEMSZ (2*STG)                       // 61440 B -> 3 CTAs/SM
#define SWZ(x) ((x) ^ (((x)>>3)&0x70))

__device__ __constant__ int c_dh[9] = {-1,-1,-1,0,0,-2,0,2,3};
__device__ __constant__ int c_dw[9] = {-3,-1,1,0,2,1,-1,0,1};

__device__ __align__(128) float  g_pooled[(size_t)NIMG*25*784];
__device__ __align__(128) __half g_in [(size_t)NIMG*784*576];
__device__ __align__(128) __half g_yA [(size_t)NIMG*784*256];
__device__ __align__(128) __half g_yB [(size_t)NIMG*784*256];
__device__ __align__(128) __half g_w1p[(size_t)81*256*64];
__device__ __align__(128) __half g_w2p[(size_t)36*256*64];
__device__ __align__(128) __half g_w3p[(size_t)36*256*64];
__device__ __align__(128) __half g_w4p[(size_t)36*256*64];

__device__ __forceinline__ uint32_t smem_u32(const void* p) {
    uint32_t a;
    asm("{ .reg .u64 t; cvta.to.shared.u64 t, %1; cvt.u32.u64 %0, t; }" : "=r"(a) : "l"(p));
    return a;
}
__device__ __forceinline__ void cpa(uint32_t dst, const void* src, uint32_t sz) {
    asm volatile("cp.async.cg.shared.global [%0], [%1], 16, %2;" :: "r"(dst), "l"(src), "r"(sz));
}
#define CP_COMMIT() asm volatile("cp.async.commit_group;" ::: "memory")
#define CP_WAIT0()  asm volatile("cp.async.wait_group 0;" ::: "memory")
#define LDSM4(r,a) asm volatile("ldmatrix.sync.aligned.m8n8.x4.shared.b16 {%0,%1,%2,%3}, [%4];" \
    : "=r"((r)[0]),"=r"((r)[1]),"=r"((r)[2]),"=r"((r)[3]) : "r"(a))
#define LDSM2(r,a) asm volatile("ldmatrix.sync.aligned.m8n8.x2.shared.b16 {%0,%1}, [%2];" \
    : "=r"((r)[0]),"=r"((r)[1]) : "r"(a))
#define MMA(d,a,b) asm volatile( \
    "mma.sync.aligned.m16n8k16.row.col.f32.f16.f16.f32 {%0,%1,%2,%3}, {%4,%5,%6,%7}, {%8,%9}, {%0,%1,%2,%3};" \
    : "+f"((d)[0]),"+f"((d)[1]),"+f"((d)[2]),"+f"((d)[3]) \
    : "r"((a)[0]),"r"((a)[1]),"r"((a)[2]),"r"((a)[3]),"r"((b)[0]),"r"((b)[1]))

// ---------------- prepass kernels ----------------
__global__ void pool_kernel(const float* __restrict__ in, float* __restrict__ out) {
    int idx = blockIdx.x * blockDim.x + threadIdx.x;
    if (idx >= NIMG*25*784) return;
    int plane = idx / 784, rem = idx % 784;
    int r = rem / 28, c = rem % 28;
    const float* p = in + ((size_t)plane*112 + r*4)*112 + c*4;
    float m = -INFINITY;
#pragma unroll
    for (int i = 0; i < 4; i++)
#pragma unroll
        for (int j = 0; j < 4; j++) m = fmaxf(m, p[i*112+j]);
    out[idx] = m;
}

// features+pooled (NCHW f32) -> g_in [n][pix][576] fp16
__global__ void pack_input(const float* __restrict__ feat, const float* __restrict__ pooled,
                           __half* __restrict__ out) {
    __shared__ float tile[32][113];
    int pt = blockIdx.x, ct = blockIdx.y, n = blockIdx.z, tid = threadIdx.x;
    for (int idx = tid; idx < 32*112; idx += 256) {
        int cl = idx / 112, pl = idx % 112;
        int c = ct*32 + cl, p = pt*112 + pl;
        float v = 0.f;
        if (c < 512) v = feat[((size_t)n*512 + c)*784 + p];
        else if (c < C1) v = pooled[((size_t)n*25 + (c-512))*784 + p];
        tile[cl][pl] = v;
    }
    __syncthreads();
    for (int idx = tid; idx < 112*32; idx += 256) {
        int pl = idx / 32, cl = idx % 32;
        out[((size_t)n*784 + pt*112 + pl)*576 + ct*32 + cl] = __float2half(tile[cl][pl]);
    }
}

// All 4 weight tensors: [o][c][9] f32 -> [stage][o][64] fp16
__global__ void pack_w_all(const float* __restrict__ w1, const float* __restrict__ w2,
                           const float* __restrict__ w3, const float* __restrict__ w4,
                           __half* __restrict__ o1, __half* __restrict__ o2,
                           __half* __restrict__ o3, __half* __restrict__ o4) {
    int idx = blockIdx.x * blockDim.x + threadIdx.x;
    const int SZ1 = 81*16384, SZ = 36*16384;
    const float* w; __half* out; int C, loc;
    if (idx < SZ1)                { w = w1; out = o1; C = C1;  loc = idx; }
    else if (idx < SZ1 + SZ)      { w = w2; out = o2; C = 256; loc = idx - SZ1; }
    else if (idx < SZ1 + 2*SZ)    { w = w3; out = o3; C = 256; loc = idx - SZ1 - SZ; }
    else if (idx < SZ1 + 3*SZ)    { w = w4; out = o4; C = 256; loc = idx - SZ1 - 2*SZ; }
    else return;
    int ch = loc & 63, o = (loc >> 6) & 255, t = (loc >> 14) % 9, chunk = loc / (9*16384);
    int c = chunk*64 + ch;
    float v = (c < C) ? w[((size_t)o*C + c)*9 + t] : 0.f;
    out[((size_t)(chunk*9+t)*256 + o)*64 + ch] = __float2half(v);
}

// ---------------- main HMMA conv layer (single fp16) ----------------
// D[128 o][112 pix] per CTA; 256 threads, warp grid 4(m) x 2(n): 32o x 56pix per warp.
// Pure fp16 operands, fp32 accumulate. 3 CTAs/SM.
__global__ __launch_bounds__(256, 3)
void conv_mma(const __half* __restrict__ actIn, int CpadIn, int nChunks,
              const __half* __restrict__ wPack,
              __half* __restrict__ actOut, float* __restrict__ fOut)
{
    extern __shared__ __align__(1024) char smem[];
    uint32_t sb = smem_u32(smem);
    int tid = threadIdx.x, wid = tid >> 5, lane = tid & 31;
    int rt = blockIdx.x, oBase = blockIdx.y * 128, n = blockIdx.z;
    int r0 = rt * 4;
    int wm = wid & 3, wn = wid >> 2;        // warp tile: 32 o x 56 pix

    const int nStages = nChunks * 9;

    // ---- hoisted fill addressing ----
    const int fseg = tid & 7;
    const int frow0 = tid >> 3;             // 0..31
    // A: 128 rows x 8 segs = 1024 copies / 256 thr = 4 each; rows frow0 + 32k
    const __half* aSrc0 = wPack + ((size_t)oBase + frow0)*64 + fseg*8;
    const uint32_t aDst0 = SWZ((uint32_t)(frow0*128 + fseg*16));
    // B: 112 rows x 8 segs = 896 copies; rows frow0 + 32m (m=3 valid only for frow0<16)
    int bRi[4], bCi[4];
#pragma unroll
    for (int m = 0; m < 4; m++) { int i = frow0 + 32*m; bRi[m] = i / 28; bCi[m] = i - (i/28)*28; }
    const uint32_t bDst0 = SWZ((uint32_t)(frow0*128 + fseg*16));
    const __half* bSrcN = actIn + (size_t)n*784*CpadIn + fseg*8;
    const bool bHas3 = (frow0 < 16);

    float d[2][7][4];
#pragma unroll
    for (int mi = 0; mi < 2; mi++)
#pragma unroll
        for (int ni = 0; ni < 7; ni++)
#pragma unroll
            for (int k = 0; k < 4; k++) d[mi][ni][k] = 0.f;

    auto fill = [&](int s, int buf) {
        int chunk = s / 9, t = s - chunk*9;
        int dh = c_dh[t], dw = c_dw[t];
        const __half* aS = aSrc0 + (size_t)s*256*64;
        uint32_t aD = sb + ASMO(buf) + aDst0;
#pragma unroll
        for (int k = 0; k < 4; k++)
            cpa(aD + 4096u*k, aS + 2048*k, 16);
        const __half* bS = bSrcN + chunk*64;
        uint32_t bD = sb + BSMO(buf) + bDst0;
#pragma unroll
        for (int m = 0; m < 4; m++) {
            if (m == 3 && !bHas3) break;
            int rr = r0 + bRi[m] + dh, cc = bCi[m] + dw;
            bool ok = ((unsigned)rr < 28u) && ((unsigned)cc < 28u);
            const void* src = bS + (size_t)(ok ? (rr*28 + cc) : 0) * CpadIn;
            cpa(bD + 4096u*m, src, ok ? 16 : 0);
        }
    };

    int aRow  = (lane & 15);
    int aColb = (lane >> 4) << 4;
    int bRow  = (lane & 7);
    int bColb = ((lane >> 3) & 1) << 4;

    fill(0, 0); CP_COMMIT();

    for (int s = 0; s < nStages; s++) {
        int buf = s & 1;
        CP_WAIT0();
        __syncthreads();   // orders fill(s) visibility AND compute(s-1) vs fill(s+1)
        if (s + 1 < nStages) { fill(s+1, buf ^ 1); CP_COMMIT(); }

#pragma unroll
        for (int ks = 0; ks < 4; ks++) {
            uint32_t a[2][4];
#pragma unroll
            for (int mi = 0; mi < 2; mi++) {
                uint32_t ro = (wm*32 + mi*16 + aRow) << 7;
                uint32_t co = ks*32 + aColb;
                LDSM4(a[mi], sb + ASMO(buf) + SWZ(ro + co));
            }
#pragma unroll
            for (int ni = 0; ni < 7; ni++) {
                uint32_t ro = (wn*56 + ni*8 + bRow) << 7;
                uint32_t co = ks*32 + bColb;
                uint32_t bh[2];
                LDSM2(bh, sb + BSMO(buf) + SWZ(ro + co));
                MMA(d[0][ni], a[0], bh);
                MMA(d[1][ni], a[1], bh);
            }
        }
    }

    // ---- epilogue: ReLU + store ----
    int quad = lane >> 2, four = lane & 3;
#pragma unroll
    for (int mi = 0; mi < 2; mi++)
#pragma unroll
        for (int ni = 0; ni < 7; ni++)
#pragma unroll
            for (int k = 0; k < 4; k++) {
                float v = fmaxf(d[mi][ni][k], 0.f);
                int o   = oBase + wm*32 + mi*16 + quad + ((k >> 1) << 3);
                int pix = rt*112 + wn*56 + ni*8 + four*2 + (k & 1);
                if (actOut) {
                    actOut[((size_t)n*784 + pix)*256 + o] = __float2half(v);
                } else {
                    fOut[((size_t)n*256 + o)*784 + pix] = v;
                }
            }
}

// ---------------------------------------------------------------------------
extern "C" void kernel_launch(void* const* d_in, const int* in_sizes, int n_in,
                              void* d_out, int out_size)
{
    const float* features  = (const float*)d_in[0];
    const float* fine_segm = (const float*)d_in[1];
    const float* w1 = (const float*)d_in[2];
    const float* w2 = (const float*)d_in[3];
    const float* w3 = (const float*)d_in[4];
    const float* w4 = (const float*)d_in[5];
    float* out = (float*)d_out;

    float *pooled; __half *in, *yA, *yB, *w1p, *w2p, *w3p, *w4p;
    cudaGetSymbolAddress((void**)&pooled, g_pooled);
    cudaGetSymbolAddress((void**)&in,  g_in);
    cudaGetSymbolAddress((void**)&yA,  g_yA);
    cudaGetSymbolAddress((void**)&yB,  g_yB);
    cudaGetSymbolAddress((void**)&w1p, g_w1p);
    cudaGetSymbolAddress((void**)&w2p, g_w2p);
    cudaGetSymbolAddress((void**)&w3p, g_w3p);
    cudaGetSymbolAddress((void**)&w4p, g_w4p);

    cudaFuncSetAttribute(conv_mma, cudaFuncAttributeMaxDynamicSharedMemorySize, SMEMSZ);

    pool_kernel<<<(NIMG*25*784 + 255)/256, 256>>>(fine_segm, pooled);
    pack_input<<<dim3(7,18,NIMG), 256>>>(features, pooled, in);
    {
        int total = (81 + 3*36) * 16384;
        pack_w_all<<<(total + 255)/256, 256>>>(w1, w2, w3, w4, w1p, w2p, w3p, w4p);
    }

    dim3 grid(7, 2, NIMG);   // 7 pix tiles x 2 o-halves x 128 images = 1792 CTAs
    conv_mma<<<grid, 256, SMEMSZ>>>(in, 576, 9, w1p, yA, nullptr);
    conv_mma<<<grid, 256, SMEMSZ>>>(yA, 256, 4, w2p, yB, nullptr);
    conv_mma<<<grid, 256, SMEMSZ>>>(yB, 256, 4, w3p, yA, nullptr);
    conv_mma<<<grid, 256, SMEMSZ>>>(yA, 256, 4, w4p, nullptr, out);
}

// round 17
// speedup vs baseline: 4.3216x; 1.2658x over previous
#include <cuda_runtime.h>
#include <cuda_fp16.h>
#include <cstdint>
#include <math.h>

#define NIMG 128
#define OCH 256
#define C1 537

// SMEM: double-buffered stage = A(16KB fp16 weights) + B(14KB fp16 pixels) = 30720 B
#define STG 30720
#define ASMO(b)  ((b)*STG)                   // A: 128 rows x 128B
#define BSMO(b)  ((b)*STG + 16384)           // B: 112 rows x 128B
#define SMEMSZ (2*STG)                       // 61440 B -> 3 CTAs/SM
#define SWZ(x) ((x) ^ (((x)>>3)&0x70))

__device__ __constant__ int c_dh[9] = {-1,-1,-1,0,0,-2,0,2,3};
__device__ __constant__ int c_dw[9] = {-3,-1,1,0,2,1,-1,0,1};

__device__ __align__(128) float  g_pooled[(size_t)NIMG*25*784];
__device__ __align__(128) __half g_in [(size_t)NIMG*784*576];
__device__ __align__(128) __half g_yA [(size_t)NIMG*784*256];
__device__ __align__(128) __half g_yB [(size_t)NIMG*784*256];
__device__ __align__(128) __half g_w1p[(size_t)81*256*64];
__device__ __align__(128) __half g_w2p[(size_t)36*256*64];
__device__ __align__(128) __half g_w3p[(size_t)36*256*64];
__device__ __align__(128) __half g_w4p[(size_t)36*256*64];

__device__ __forceinline__ uint32_t smem_u32(const void* p) {
    uint32_t a;
    asm("{ .reg .u64 t; cvta.to.shared.u64 t, %1; cvt.u32.u64 %0, t; }" : "=r"(a) : "l"(p));
    return a;
}
__device__ __forceinline__ void cpa(uint32_t dst, const void* src, uint32_t sz) {
    asm volatile("cp.async.cg.shared.global [%0], [%1], 16, %2;" :: "r"(dst), "l"(src), "r"(sz));
}
#define CP_COMMIT() asm volatile("cp.async.commit_group;" ::: "memory")
#define CP_WAIT0()  asm volatile("cp.async.wait_group 0;" ::: "memory")
#define LDSM4(r,a) asm volatile("ldmatrix.sync.aligned.m8n8.x4.shared.b16 {%0,%1,%2,%3}, [%4];" \
    : "=r"((r)[0]),"=r"((r)[1]),"=r"((r)[2]),"=r"((r)[3]) : "r"(a))
#define LDSM2(r,a) asm volatile("ldmatrix.sync.aligned.m8n8.x2.shared.b16 {%0,%1}, [%2];" \
    : "=r"((r)[0]),"=r"((r)[1]) : "r"(a))
#define MMA(d,a,b) asm volatile( \
    "mma.sync.aligned.m16n8k16.row.col.f32.f16.f16.f32 {%0,%1,%2,%3}, {%4,%5,%6,%7}, {%8,%9}, {%0,%1,%2,%3};" \
    : "+f"((d)[0]),"+f"((d)[1]),"+f"((d)[2]),"+f"((d)[3]) \
    : "r"((a)[0]),"r"((a)[1]),"r"((a)[2]),"r"((a)[3]),"r"((b)[0]),"r"((b)[1]))

// ---------------- prepass kernels ----------------
__global__ void pool_kernel(const float* __restrict__ in, float* __restrict__ out) {
    int idx = blockIdx.x * blockDim.x + threadIdx.x;
    if (idx >= NIMG*25*784) return;
    int plane = idx / 784, rem = idx % 784;
    int r = rem / 28, c = rem % 28;
    const float* p = in + ((size_t)plane*112 + r*4)*112 + c*4;
    float m = -INFINITY;
#pragma unroll
    for (int i = 0; i < 4; i++)
#pragma unroll
        for (int j = 0; j < 4; j++) m = fmaxf(m, p[i*112+j]);
    out[idx] = m;
}

// features+pooled (NCHW f32) -> g_in [n][pix][576] fp16
__global__ void pack_input(const float* __restrict__ feat, const float* __restrict__ pooled,
                           __half* __restrict__ out) {
    __shared__ float tile[32][113];
    int pt = blockIdx.x, ct = blockIdx.y, n = blockIdx.z, tid = threadIdx.x;
    for (int idx = tid; idx < 32*112; idx += 256) {
        int cl = idx / 112, pl = idx % 112;
        int c = ct*32 + cl, p = pt*112 + pl;
        float v = 0.f;
        if (c < 512) v = feat[((size_t)n*512 + c)*784 + p];
        else if (c < C1) v = pooled[((size_t)n*25 + (c-512))*784 + p];
        tile[cl][pl] = v;
    }
    __syncthreads();
    for (int idx = tid; idx < 112*32; idx += 256) {
        int pl = idx / 32, cl = idx % 32;
        out[((size_t)n*784 + pt*112 + pl)*576 + ct*32 + cl] = __float2half(tile[cl][pl]);
    }
}

// All 4 weight tensors: [o][c][9] f32 -> [stage][o][64] fp16
__global__ void pack_w_all(const float* __restrict__ w1, const float* __restrict__ w2,
                           const float* __restrict__ w3, const float* __restrict__ w4,
                           __half* __restrict__ o1, __half* __restrict__ o2,
                           __half* __restrict__ o3, __half* __restrict__ o4) {
    int idx = blockIdx.x * blockDim.x + threadIdx.x;
    const int SZ1 = 81*16384, SZ = 36*16384;
    const float* w; __half* out; int C, loc;
    if (idx < SZ1)                { w = w1; out = o1; C = C1;  loc = idx; }
    else if (idx < SZ1 + SZ)      { w = w2; out = o2; C = 256; loc = idx - SZ1; }
    else if (idx < SZ1 + 2*SZ)    { w = w3; out = o3; C = 256; loc = idx - SZ1 - SZ; }
    else if (idx < SZ1 + 3*SZ)    { w = w4; out = o4; C = 256; loc = idx - SZ1 - 2*SZ; }
    else return;
    int ch = loc & 63, o = (loc >> 6) & 255, t = (loc >> 14) % 9, chunk = loc / (9*16384);
    int c = chunk*64 + ch;
    float v = (c < C) ? w[((size_t)o*C + c)*9 + t] : 0.f;
    out[((size_t)(chunk*9+t)*256 + o)*64 + ch] = __float2half(v);
}

// ---------------- main HMMA conv layer (single fp16, fat warp tiles) ----------------
// D[128 o][112 pix] per CTA; 128 threads, warp grid 2(m) x 2(n): 64o x 56pix per warp.
// wf/MMA = 1.07: each B fragment feeds 4 MMAs, each A fragment 7. 3 CTAs/SM.
__global__ __launch_bounds__(128, 3)
void conv_mma(const __half* __restrict__ actIn, int CpadIn, int nChunks,
              const __half* __restrict__ wPack,
              __half* __restrict__ actOut, float* __restrict__ fOut)
{
    extern __shared__ __align__(1024) char smem[];
    uint32_t sb = smem_u32(smem);
    int tid = threadIdx.x, wid = tid >> 5, lane = tid & 31;
    int rt = blockIdx.x, oBase = blockIdx.y * 128, n = blockIdx.z;
    int r0 = rt * 4;
    int wm = wid & 1, wn = wid >> 1;        // warp tile: 64 o x 56 pix

    const int nStages = nChunks * 9;

    // ---- hoisted fill addressing (128 threads) ----
    const int fseg = tid & 7;
    const int frow0 = tid >> 3;             // 0..15
    // A: 128 rows x 8 segs = 1024 copies / 128 thr = 8 each; rows frow0 + 16k
    const __half* aSrc0 = wPack + ((size_t)oBase + frow0)*64 + fseg*8;
    const uint32_t aDst0 = SWZ((uint32_t)(frow0*128 + fseg*16));
    // B: 112 rows x 8 segs = 896 copies / 128 = 7 each; rows frow0 + 16m
    int bRi[7], bCi[7];
#pragma unroll
    for (int m = 0; m < 7; m++) { int i = frow0 + 16*m; bRi[m] = i / 28; bCi[m] = i - (i/28)*28; }
    const uint32_t bDst0 = SWZ((uint32_t)(frow0*128 + fseg*16));
    const __half* bSrcN = actIn + (size_t)n*784*CpadIn + fseg*8;

    float d[4][7][4];
#pragma unroll
    for (int mi = 0; mi < 4; mi++)
#pragma unroll
        for (int ni = 0; ni < 7; ni++)
#pragma unroll
            for (int k = 0; k < 4; k++) d[mi][ni][k] = 0.f;

    auto fill = [&](int s, int buf) {
        int chunk = s / 9, t = s - chunk*9;
        int dh = c_dh[t], dw = c_dw[t];
        const __half* aS = aSrc0 + (size_t)s*256*64;
        uint32_t aD = sb + ASMO(buf) + aDst0;
#pragma unroll
        for (int k = 0; k < 8; k++)
            cpa(aD + 2048u*k, aS + 1024*k, 16);
        const __half* bS = bSrcN + chunk*64;
        uint32_t bD = sb + BSMO(buf) + bDst0;
#pragma unroll
        for (int m = 0; m < 7; m++) {
            int rr = r0 + bRi[m] + dh, cc = bCi[m] + dw;
            bool ok = ((unsigned)rr < 28u) && ((unsigned)cc < 28u);
            const void* src = bS + (size_t)(ok ? (rr*28 + cc) : 0) * CpadIn;
            cpa(bD + 2048u*m, src, ok ? 16 : 0);
        }
    };

    int aRow  = (lane & 15);
    int aColb = (lane >> 4) << 4;
    int bRow  = (lane & 7);
    int bColb = ((lane >> 3) & 1) << 4;

    fill(0, 0); CP_COMMIT();

    for (int s = 0; s < nStages; s++) {
        int buf = s & 1;
        CP_WAIT0();
        __syncthreads();   // orders fill(s) visibility AND compute(s-1) vs fill(s+1)
        if (s + 1 < nStages) { fill(s+1, buf ^ 1); CP_COMMIT(); }

#pragma unroll
        for (int ks = 0; ks < 4; ks++) {
            uint32_t a[4][4];
#pragma unroll
            for (int mi = 0; mi < 4; mi++) {
                uint32_t ro = (wm*64 + mi*16 + aRow) << 7;
                uint32_t co = ks*32 + aColb;
                LDSM4(a[mi], sb + ASMO(buf) + SWZ(ro + co));
            }
#pragma unroll
            for (int ni = 0; ni < 7; ni++) {
                uint32_t ro = (wn*56 + ni*8 + bRow) << 7;
                uint32_t co = ks*32 + bColb;
                uint32_t bh[2];
                LDSM2(bh, sb + BSMO(buf) + SWZ(ro + co));
                MMA(d[0][ni], a[0], bh);
                MMA(d[1][ni], a[1], bh);
                MMA(d[2][ni], a[2], bh);
                MMA(d[3][ni], a[3], bh);
            }
        }
    }

    // ---- epilogue: ReLU + store ----
    int quad = lane >> 2, four = lane & 3;
#pragma unroll
    for (int mi = 0; mi < 4; mi++)
#pragma unroll
        for (int ni = 0; ni < 7; ni++)
#pragma unroll
            for (int k = 0; k < 4; k++) {
                float v = fmaxf(d[mi][ni][k], 0.f);
                int o   = oBase + wm*64 + mi*16 + quad + ((k >> 1) << 3);
                int pix = rt*112 + wn*56 + ni*8 + four*2 + (k & 1);
                if (actOut) {
                    actOut[((size_t)n*784 + pix)*256 + o] = __float2half(v);
                } else {
                    fOut[((size_t)n*256 + o)*784 + pix] = v;
                }
            }
}

// ---------------------------------------------------------------------------
extern "C" void kernel_launch(void* const* d_in, const int* in_sizes, int n_in,
                              void* d_out, int out_size)
{
    const float* features  = (const float*)d_in[0];
    const float* fine_segm = (const float*)d_in[1];
    const float* w1 = (const float*)d_in[2];
    const float* w2 = (const float*)d_in[3];
    const float* w3 = (const float*)d_in[4];
    const float* w4 = (const float*)d_in[5];
    float* out = (float*)d_out;

    float *pooled; __half *in, *yA, *yB, *w1p, *w2p, *w3p, *w4p;
    cudaGetSymbolAddress((void**)&pooled, g_pooled);
    cudaGetSymbolAddress((void**)&in,  g_in);
    cudaGetSymbolAddress((void**)&yA,  g_yA);
    cudaGetSymbolAddress((void**)&yB,  g_yB);
    cudaGetSymbolAddress((void**)&w1p, g_w1p);
    cudaGetSymbolAddress((void**)&w2p, g_w2p);
    cudaGetSymbolAddress((void**)&w3p, g_w3p);
    cudaGetSymbolAddress((void**)&w4p, g_w4p);

    cudaFuncSetAttribute(conv_mma, cudaFuncAttributeMaxDynamicSharedMemorySize, SMEMSZ);

    pool_kernel<<<(NIMG*25*784 + 255)/256, 256>>>(fine_segm, pooled);
    pack_input<<<dim3(7,18,NIMG), 256>>>(features, pooled, in);
    {
        int total = (81 + 3*36) * 16384;
        pack_w_all<<<(total + 255)/256, 256>>>(w1, w2, w3, w4, w1p, w2p, w3p, w4p);
    }

    dim3 grid(7, 2, NIMG);   // 7 pix tiles x 2 o-halves x 128 images = 1792 CTAs
    conv_mma<<<grid, 128, SMEMSZ>>>(in, 576, 9, w1p, yA, nullptr);
    conv_mma<<<grid, 128, SMEMSZ>>>(yA, 256, 4, w2p, yB, nullptr);
    conv_mma<<<grid, 128, SMEMSZ>>>(yB, 256, 4, w3p, yA, nullptr);
    conv_mma<<<grid, 128, SMEMSZ>>>(yA, 256, 4, w4p, nullptr, out);
}